// round 3
// baseline (speedup 1.0000x reference)
#include <cuda_runtime.h>
#include <cuda_bf16.h>

// ============================================================================
// SSIM loss, separable Gaussian, 4-signal (u=x+y, v=x-y) f32x2-packed form.
//
// Per tile (64x64x3, contiguous 49152 B) per channel:
//   signals u, v, u^2, v^2 -> horizontal 11-tap (64x64 -> 64x54, f32x2 pairs)
//                           -> vertical   11-tap (64x54 -> 54x54)
//   p=conv(u)=mu1+mu2, q=conv(v)=mu1-mu2, Su=conv(u^2), Sv=conv(v^2)
//   A=2*mu1*mu2=(p^2-q^2)/2, B=mu1^2+mu2^2=(p^2+q^2)/2
//   num=(A+C1)*((Su-Sv)/2 - A + C2),  den=(B+C1)*((Su+Sv)/2 - B + C2)
// Output: 1 - mean over 2048*3*54*54 values. Single fused kernel.
// ============================================================================

static constexpr int THREADS = 384;
static constexpr int NBLK    = 2048;
static constexpr float C1 = 1.0e-4f;   // (0.01*L)^2, L = 1
static constexpr float C2 = 9.0e-4f;

__device__ constexpr float G[11] = {
    0.00102840f, 0.00759878f, 0.03600077f, 0.10936042f, 0.21300560f,
    0.26601170f,
    0.21300560f, 0.10936042f, 0.03600077f, 0.00759878f, 0.00102840f
};

typedef unsigned long long u64;

__device__ __forceinline__ u64 pack2(float a, float b) {
    u64 r;
    asm("mov.b64 %0, {%1, %2};" : "=l"(r) : "f"(a), "f"(b));
    return r;
}
__device__ __forceinline__ void unpack2(u64 p, float& a, float& b) {
    asm("mov.b64 {%0, %1}, %2;" : "=f"(a), "=f"(b) : "l"(p));
}
__device__ __forceinline__ u64 fma2(u64 a, u64 b, u64 c) {
    u64 d;
    asm("fma.rn.f32x2 %0, %1, %2, %3;" : "=l"(d) : "l"(a), "l"(b), "l"(c));
    return d;
}
__device__ __forceinline__ u64 mul2(u64 a, u64 b) {
    u64 d;
    asm("mul.rn.f32x2 %0, %1, %2;" : "=l"(d) : "l"(a), "l"(b));
    return d;
}

struct SmemLayout {
    float2 plane[64][65];   // (u, v) per pixel, +1 pad col     : 33,280 B
    float4 hb[64][54];      // (p, q, Su, Sv) after h-pass      : 55,296 B
};
static constexpr int SMEM_BYTES = (int)sizeof(SmemLayout);  // 88,576 B

__device__ float        g_part[NBLK];
__device__ unsigned int g_count = 0;

__global__ __launch_bounds__(THREADS, 2)
void ssim_main(const float* __restrict__ pred, const float* __restrict__ gt,
               float* __restrict__ out)
{
    extern __shared__ unsigned char smem_raw[];
    SmemLayout& s = *reinterpret_cast<SmemLayout*>(smem_raw);

    const int b   = blockIdx.x;
    const int tid = threadIdx.x;
    const float* pb = pred + (size_t)b * 12288;
    const float* gb = gt   + (size_t)b * 12288;

    // packed weights (constant-folded in the unrolled loops)
    u64 W[11];
    #pragma unroll
    for (int k = 0; k < 11; ++k) W[k] = pack2(G[k], G[k]);

    float local = 0.0f;

    for (int ch = 0; ch < 3; ++ch) {
        __syncthreads();  // prior v-pass done with hb; plane free since earlier

        // ---- load channel plane, form (u, v) = (x+y, x-y)
        for (int i = tid; i < 4096; i += THREADS) {
            const float x = pb[i * 3 + ch];
            const float y = gb[i * 3 + ch];
            s.plane[i >> 6][i & 63] = make_float2(x + y, x - y);
        }
        __syncthreads();

        // ---- horizontal pass: 64 rows x 6 segments of 9 outputs
        {
            const int r  = tid / 6;
            const int c0 = (tid % 6) * 9;
            const u64* prow = reinterpret_cast<const u64*>(&s.plane[r][0]);

            u64 auv[9], asq[9];
            #pragma unroll
            for (int o = 0; o < 9; ++o) { auv[o] = 0ull; asq[o] = 0ull; }

            #pragma unroll
            for (int j = 0; j < 19; ++j) {
                const u64 uv = prow[c0 + j];        // LDS.64
                const u64 sq = mul2(uv, uv);
                #pragma unroll
                for (int k = 0; k < 11; ++k) {
                    const int o = j - k;            // compile-time pruned
                    if (o >= 0 && o < 9) {
                        auv[o] = fma2(W[k], uv, auv[o]);
                        asq[o] = fma2(W[k], sq, asq[o]);
                    }
                }
            }
            #pragma unroll
            for (int o = 0; o < 9; ++o) {
                float p, q, su, sv;
                unpack2(auv[o], p, q);
                unpack2(asq[o], su, sv);
                s.hb[r][c0 + o] = make_float4(p, q, su, sv);  // STS.128
            }
        }
        __syncthreads();

        // ---- vertical pass + ssim: 54 cols x 6 segments of 9 rows
        if (tid < 324) {
            const int c  = tid % 54;
            const int r0 = (tid / 54) * 9;

            u64 auv[9], asq[9];
            #pragma unroll
            for (int o = 0; o < 9; ++o) { auv[o] = 0ull; asq[o] = 0ull; }

            #pragma unroll
            for (int j = 0; j < 19; ++j) {
                const ulonglong2 t =
                    *reinterpret_cast<const ulonglong2*>(&s.hb[r0 + j][c]); // LDS.128
                #pragma unroll
                for (int k = 0; k < 11; ++k) {
                    const int o = j - k;
                    if (o >= 0 && o < 9) {
                        auv[o] = fma2(W[k], t.x, auv[o]);
                        asq[o] = fma2(W[k], t.y, asq[o]);
                    }
                }
            }
            #pragma unroll
            for (int o = 0; o < 9; ++o) {
                float p, q, su, sv;
                unpack2(auv[o], p, q);
                unpack2(asq[o], su, sv);
                const float P = p * p, Q = q * q;
                const float A = 0.5f * (P - Q);           // 2*mu1*mu2
                const float B = 0.5f * (P + Q);           // mu1^2+mu2^2
                const float num = (A + C1) * (fmaf(0.5f, su - sv, C2) - A);
                const float den = (B + C1) * (fmaf(0.5f, su + sv, C2) - B);
                local += __fdividef(num, den);
            }
        }
    }

    // ---- fixed-order block reduction -> per-tile partial
    __syncthreads();
    #pragma unroll
    for (int off = 16; off > 0; off >>= 1)
        local += __shfl_down_sync(0xffffffffu, local, off);

    __shared__ float red[THREADS / 32];
    __shared__ unsigned int ticket;
    if ((tid & 31) == 0) red[tid >> 5] = local;
    __syncthreads();
    if (tid == 0) {
        float sum = 0.0f;
        #pragma unroll
        for (int w = 0; w < THREADS / 32; ++w) sum += red[w];
        g_part[b] = sum;
        __threadfence();
        ticket = atomicAdd(&g_count, 1u);
    }
    __syncthreads();

    // ---- last block performs the deterministic global reduction
    if (ticket == NBLK - 1) {
        float sum = 0.0f;
        for (int i = tid; i < NBLK; i += THREADS) sum += g_part[i];  // fixed order
        #pragma unroll
        for (int off = 16; off > 0; off >>= 1)
            sum += __shfl_down_sync(0xffffffffu, sum, off);
        if ((tid & 31) == 0) red[tid >> 5] = sum;
        __syncthreads();
        if (tid == 0) {
            float t = 0.0f;
            #pragma unroll
            for (int w = 0; w < THREADS / 32; ++w) t += red[w];
            // N = 2048 * 3 * 54 * 54 = 17,915,904
            out[0] = 1.0f - t * (1.0f / 17915904.0f);
            g_count = 0;   // reset for next graph replay
        }
    }
}

extern "C" void kernel_launch(void* const* d_in, const int* in_sizes, int n_in,
                              void* d_out, int out_size)
{
    const float* pred = (const float*)d_in[0];
    const float* gt   = (const float*)d_in[1];
    float* out        = (float*)d_out;

    cudaFuncSetAttribute(ssim_main, cudaFuncAttributeMaxDynamicSharedMemorySize,
                         SMEM_BYTES);
    ssim_main<<<NBLK, THREADS, SMEM_BYTES>>>(pred, gt, out);
}